// round 15
// baseline (speedup 1.0000x reference)
#include <cuda_runtime.h>
#include <cuda_fp16.h>
#include <cstdint>

// QLoRA linear via mma.sync fp16 single-term GEMM.
// Pre: fused NF4 dequant + tensor-core LoRA-A projection (+x->fp16), KSPL=8.
// Main: 128x128 HMMA GEMM with warp-desynced ks ordering to break the
// LDSM/MMA phase-lock across co-resident warps.

#define M_DIM 8192
#define N_DIM 4096
#define K_DIM 4096
#define R_DIM 16
#define TM 128
#define TN 128
#define BK 64
#define NK (K_DIM / BK)   // 64

#define TILEB 16384           // 128 rows x 128B (SW128)
#define STAGEB (2 * TILEB)    // X, W = 32768
#define NSTG 3
#define SMEMB (NSTG * STAGEB) // 98304

#define KSPL 8
#define KS_LEN (K_DIM / KSPL)                  // 512
#define LORA_BLKS (M_DIM / 128 * KSPL)         // 512
#define DEQ_BLKS (N_DIM * K_DIM / 2048)        // 8192

// ---- device scratch ----
__device__ float g_axp[M_DIM * R_DIM * KSPL];
__device__ __half g_xh[(size_t)M_DIM * K_DIM];
__device__ __half g_wh[(size_t)N_DIM * K_DIM];

__constant__ float c_nf4[16] = {
    -1.0f, -0.6961928009986877f, -0.5250730514526367f, -0.39491748809814453f,
    -0.28444138169288635f, -0.18477343022823334f, -0.09105003625154495f, 0.0f,
    0.07958029955625534f, 0.16093020141124725f, 0.24611230194568634f,
    0.33791524171829224f, 0.44070982933044434f, 0.5626170039176941f,
    0.7229568362236023f, 1.0f};

// ---------------------------------------------------------------------------
__device__ __forceinline__ uint32_t smem_u32(const void* p) {
  return (uint32_t)__cvta_generic_to_shared((void*)p);
}
__device__ __forceinline__ uint32_t swz(uint32_t off) {
  return off ^ (((off >> 7) & 7u) << 4);
}
__device__ __forceinline__ void cpa16(uint32_t s, const void* g) {
  asm volatile("cp.async.cg.shared.global [%0], [%1], 16;" :: "r"(s), "l"(g));
}
__device__ __forceinline__ void ldsm4(uint32_t (&r)[4], uint32_t addr) {
  asm volatile(
      "ldmatrix.sync.aligned.m8n8.x4.shared.b16 {%0,%1,%2,%3}, [%4];"
      : "=r"(r[0]), "=r"(r[1]), "=r"(r[2]), "=r"(r[3]) : "r"(addr));
}
__device__ __forceinline__ void mma_f16(float (&d)[4], const uint32_t (&a)[4],
                                        uint32_t b0, uint32_t b1) {
  asm volatile(
      "mma.sync.aligned.m16n8k16.row.col.f32.f16.f16.f32 "
      "{%0,%1,%2,%3}, {%4,%5,%6,%7}, {%8,%9}, {%0,%1,%2,%3};"
      : "+f"(d[0]), "+f"(d[1]), "+f"(d[2]), "+f"(d[3])
      : "r"(a[0]), "r"(a[1]), "r"(a[2]), "r"(a[3]), "r"(b0), "r"(b1));
}

// ---------------------------------------------------------------------------
// Fused precompute (R12 structure).
// ---------------------------------------------------------------------------
__global__ __launch_bounds__(256) void fused_pre_kernel(
    const float* __restrict__ x, const int* __restrict__ codes,
    const float* __restrict__ absmax, const float* __restrict__ A) {
  __shared__ char smbuf[16384 + 2048];  // Xs [128 x 128B] + As [16 x 128B]
  const int tid = threadIdx.x;

  if (blockIdx.x >= LORA_BLKS) {
    // ---- dequant: 8 codes per thread ----
    __shared__ float lut[16];
    if (tid < 16) lut[tid] = c_nf4[tid];
    __syncthreads();
    size_t i8 = (size_t)(blockIdx.x - LORA_BLKS) * 256 + tid;
    const int4* c4p = (const int4*)codes;
    int4 c0 = c4p[i8 * 2];
    int4 c1 = c4p[i8 * 2 + 1];
    size_t e0 = i8 * 8;
    int row = (int)(e0 >> 12);
    int col = (int)(e0 & 4095);
    float am = absmax[row * (K_DIM / 64) + (col >> 6)];
    __half h[8] = {
        __float2half_rn(lut[c0.x] * am), __float2half_rn(lut[c0.y] * am),
        __float2half_rn(lut[c0.z] * am), __float2half_rn(lut[c0.w] * am),
        __float2half_rn(lut[c1.x] * am), __float2half_rn(lut[c1.y] * am),
        __float2half_rn(lut[c1.z] * am), __float2half_rn(lut[c1.w] * am)};
    *(uint4*)&g_wh[e0] = *(uint4*)h;
    return;
  }

  // ---- lora via tensor cores: 128 m-rows x 512 k ----
  const int bx = blockIdx.x;
  const int m0 = (bx & 63) * 128;
  const int ks = bx >> 6;
  const int wid = tid >> 5;
  const int lane = tid & 31;
  const int rl = lane & 15;
  const int chalf = (lane >> 4) * 16;
  const uint32_t sbase = smem_u32(smbuf);

  const int xrow = wid * 16 + rl;
  const uint32_t offX = (uint32_t)(xrow * 128 + (chalf ^ ((xrow & 7) << 4)));
  const uint32_t offA =
      16384u + (uint32_t)(rl * 128 + (chalf ^ ((rl & 7) << 4)));

  float acc[2][4];
#pragma unroll
  for (int i = 0; i < 2; i++)
#pragma unroll
    for (int e = 0; e < 4; e++) acc[i][e] = 0.f;

  for (int c8 = 0; c8 < 8; c8++) {
    const int kc = ks * KS_LEN + c8 * 64;
    {
      int r = tid >> 4;
      int c4 = (tid & 15) * 4;
      float4 v = *(const float4*)&A[r * K_DIM + kc + c4];
      __half h[4] = {__float2half_rn(v.x), __float2half_rn(v.y),
                     __float2half_rn(v.z), __float2half_rn(v.w)};
      *(uint2*)(smbuf + 16384 + swz((uint32_t)(r * 128 + c4 * 2))) =
          *(uint2*)h;
    }
#pragma unroll
    for (int i = 0; i < 8; i++) {
      int idx = tid + i * 256;
      int row = idx >> 4;
      int c4 = (idx & 15) * 4;
      size_t gofs = (size_t)(m0 + row) * K_DIM + kc + c4;
      float4 v = *(const float4*)&x[gofs];
      __half h[4] = {__float2half_rn(v.x), __float2half_rn(v.y),
                     __float2half_rn(v.z), __float2half_rn(v.w)};
      *(uint2*)&g_xh[gofs] = *(uint2*)h;
      *(uint2*)(smbuf + swz((uint32_t)(row * 128 + c4 * 2))) = *(uint2*)h;
    }
    __syncthreads();
#pragma unroll
    for (int kst = 0; kst < 4; kst++) {
      const uint32_t kx = (uint32_t)(kst << 5);
      uint32_t af[4], bf[4];
      ldsm4(af, sbase + (offX ^ kx));
      ldsm4(bf, sbase + (offA ^ kx));
      mma_f16(acc[0], af, bf[0], bf[2]);
      mma_f16(acc[1], af, bf[1], bf[3]);
    }
    __syncthreads();
  }

  const int mrow = m0 + wid * 16 + (lane >> 2);
  const int cb = (lane & 3) * 2;
#pragma unroll
  for (int ni = 0; ni < 2; ni++) {
    int rc = cb + ni * 8;
    g_axp[((size_t)mrow * R_DIM + rc) * KSPL + ks] = acc[ni][0];
    g_axp[((size_t)mrow * R_DIM + rc + 1) * KSPL + ks] = acc[ni][1];
    g_axp[((size_t)(mrow + 8) * R_DIM + rc) * KSPL + ks] = acc[ni][2];
    g_axp[((size_t)(mrow + 8) * R_DIM + rc + 1) * KSPL + ks] = acc[ni][3];
  }
}

// ---------------------------------------------------------------------------
// Main HMMA GEMM: 128x128 tile, BK=64, 3-stage cp.async, warp-desynced ks.
// ---------------------------------------------------------------------------
__global__ __launch_bounds__(256, 2) void qlora_mma_kernel(
    const float* __restrict__ Bw, float* __restrict__ out) {
  extern __shared__ char sm[];
  const int tid = threadIdx.x;
  const int wid = tid >> 5;
  const int lane = tid & 31;
  const int n0 = blockIdx.x * TN;
  const int m0 = blockIdx.y * TM;
  const int warp_m0 = (wid >> 2) * 64;
  const int warp_n0 = (wid & 3) * 32;
  const uint32_t sbase = smem_u32(sm);
  // warps sharing an SMSP (wid, wid+4) get rotations differing by 2
  const int rot = (wid >> 1) & 3;

  const __half* Xh = g_xh + (size_t)m0 * K_DIM;
  const __half* Wh = g_wh + (size_t)n0 * K_DIM;

  uint32_t so[4];
  size_t go[4];
#pragma unroll
  for (int j = 0; j < 4; j++) {
    int c = tid + j * 256;
    int row = c >> 3, cc = c & 7;
    go[j] = (size_t)row * K_DIM + cc * 8;
    so[j] = swz((uint32_t)(row * 128 + cc * 16));
  }

#define LOAD_STAGE(SB, KT)                                                     \
  do {                                                                         \
    uint32_t _sb = (SB);                                                       \
    int _kt = (KT);                                                            \
    cpa16(_sb + so[0], Xh + go[0] + _kt);                                      \
    cpa16(_sb + so[1], Xh + go[1] + _kt);                                      \
    cpa16(_sb + so[2], Xh + go[2] + _kt);                                      \
    cpa16(_sb + so[3], Xh + go[3] + _kt);                                      \
    cpa16(_sb + TILEB + so[0], Wh + go[0] + _kt);                              \
    cpa16(_sb + TILEB + so[1], Wh + go[1] + _kt);                              \
    cpa16(_sb + TILEB + so[2], Wh + go[2] + _kt);                              \
    cpa16(_sb + TILEB + so[3], Wh + go[3] + _kt);                              \
  } while (0)

  const int rl = lane & 15;
  const int chalf = (lane >> 4) * 16;
  uint32_t offA[4], offB[2];
#pragma unroll
  for (int mi = 0; mi < 4; mi++) {
    int row = warp_m0 + mi * 16 + rl;
    offA[mi] = (uint32_t)(row * 128 + (chalf ^ ((row & 7) << 4)));
  }
#pragma unroll
  for (int np = 0; np < 2; np++) {
    int row = warp_n0 + np * 16 + rl;
    offB[np] = TILEB + (uint32_t)(row * 128 + (chalf ^ ((row & 7) << 4)));
  }

  float acc[4][4][4];
#pragma unroll
  for (int i = 0; i < 4; i++)
#pragma unroll
    for (int j = 0; j < 4; j++)
#pragma unroll
      for (int e = 0; e < 4; e++) acc[i][j][e] = 0.f;

  LOAD_STAGE(sbase, 0);
  asm volatile("cp.async.commit_group;" ::: "memory");
  LOAD_STAGE(sbase + STAGEB, BK);
  asm volatile("cp.async.commit_group;" ::: "memory");

  int slot = 0, wslot = 2;
  for (int k = 0; k < NK; k++) {
    asm volatile("cp.async.wait_group 1;" ::: "memory");
    __syncthreads();

    if (k + 2 < NK) LOAD_STAGE(sbase + wslot * STAGEB, (k + 2) * BK);
    asm volatile("cp.async.commit_group;" ::: "memory");

    const uint32_t sb = sbase + slot * STAGEB;
#pragma unroll
    for (int ksi = 0; ksi < 4; ksi++) {
      const int ks = (ksi + rot) & 3;
      const uint32_t kx = (uint32_t)(ks << 5);
      uint32_t bh[2][4], af[4][4];
      ldsm4(bh[0], sb + (offB[0] ^ kx));
      ldsm4(bh[1], sb + (offB[1] ^ kx));
#pragma unroll
      for (int mi = 0; mi < 4; mi++) ldsm4(af[mi], sb + (offA[mi] ^ kx));
#pragma unroll
      for (int mi = 0; mi < 4; mi++)
#pragma unroll
        for (int ni = 0; ni < 4; ni++)
          mma_f16(acc[mi][ni], af[mi], bh[ni >> 1][ni & 1],
                  bh[ni >> 1][2 + (ni & 1)]);
    }

    slot = (slot == 2) ? 0 : slot + 1;
    wslot = (wslot == 2) ? 0 : wslot + 1;
  }

  // ---- epilogue: reduce lora partials + LoRA + store ----
  asm volatile("cp.async.wait_all;" ::: "memory");
  __syncthreads();

  float* axs = (float*)sm;                    // [128][16]
  float* bs = (float*)(sm + 128 * 16 * 4);    // [128] stride 17
  for (int j = tid; j < TM * R_DIM; j += 256) {
    const float4* p =
        (const float4*)&g_axp[((size_t)m0 * R_DIM + j) * KSPL];
    float4 a = p[0], b = p[1];
    axs[j] =
        2.0f * (((a.x + a.y) + (a.z + a.w)) + ((b.x + b.y) + (b.z + b.w)));
  }
  for (int j = tid; j < TN * R_DIM; j += 256) {
    int col = j >> 4, r = j & 15;
    bs[col * 17 + r] = Bw[(size_t)(n0 + col) * R_DIM + r];
  }
  __syncthreads();

  const int r0 = lane >> 2;
  const int cbase = warp_n0 + (lane & 3) * 2;
#pragma unroll
  for (int mi = 0; mi < 4; mi++) {
#pragma unroll
    for (int half = 0; half < 2; half++) {
      const int mr = warp_m0 + mi * 16 + r0 + half * 8;
      float axr[16];
      *(float4*)&axr[0] = *(const float4*)&axs[mr * 16];
      *(float4*)&axr[4] = *(const float4*)&axs[mr * 16 + 4];
      *(float4*)&axr[8] = *(const float4*)&axs[mr * 16 + 8];
      *(float4*)&axr[12] = *(const float4*)&axs[mr * 16 + 12];
      float* orow = out + (size_t)(m0 + mr) * N_DIM + n0;
#pragma unroll
      for (int ni = 0; ni < 4; ni++) {
        const int c = cbase + ni * 8;
        const float* b0 = &bs[c * 17];
        const float* b1 = &bs[(c + 1) * 17];
        float l0 = 0.f, l1 = 0.f;
#pragma unroll
        for (int r = 0; r < 16; r++) {
          l0 += axr[r] * b0[r];
          l1 += axr[r] * b1[r];
        }
        float2 v = make_float2(acc[mi][ni][half * 2 + 0] + l0,
                               acc[mi][ni][half * 2 + 1] + l1);
        *(float2*)&orow[c] = v;
      }
    }
  }
}

// ---------------------------------------------------------------------------
extern "C" void kernel_launch(void* const* d_in, const int* in_sizes, int n_in,
                              void* d_out, int out_size) {
  const float* x = (const float*)d_in[0];
  const int* codes = (const int*)d_in[1];
  const float* absmax = (const float*)d_in[2];
  const float* A = (const float*)d_in[3];
  const float* Bw = (const float*)d_in[4];
  float* out = (float*)d_out;

  cudaFuncSetAttribute(qlora_mma_kernel,
                       cudaFuncAttributeMaxDynamicSharedMemorySize, SMEMB);

  fused_pre_kernel<<<LORA_BLKS + DEQ_BLKS, 256>>>(x, codes, absmax, A);

  dim3 grid(N_DIM / TN, M_DIM / TM);
  qlora_mma_kernel<<<grid, 256, SMEMB>>>(Bw, out);
}

// round 16
// speedup vs baseline: 1.0376x; 1.0376x over previous
#include <cuda_runtime.h>
#include <cuda_fp16.h>
#include <cstdint>

// QLoRA linear via mma.sync fp16 single-term GEMM — converged R12 config.
// out = fp16(x) @ fp16(dequant_nf4(w))^T + 2.0*(x@A^T)@B^T
// Pre: fused NF4 dequant (8 codes/thread) + tensor-core LoRA-A projection
//      (+x->fp16 conversion), KSPL=8, then a tiny deterministic reduce.
// Main: 128x128 HMMA GEMM, BK=64, 3-stage cp.async, SW128 smem; runs at the
//       measured sm_103a mma.sync dispatch floor (~190 TMAC/s).

#define M_DIM 8192
#define N_DIM 4096
#define K_DIM 4096
#define R_DIM 16
#define TM 128
#define TN 128
#define BK 64
#define NK (K_DIM / BK)   // 64

#define TILEB 16384           // 128 rows x 128B (SW128)
#define STAGEB (2 * TILEB)    // X, W = 32768
#define NSTG 3
#define SMEMB (NSTG * STAGEB) // 98304

#define KSPL 8
#define KS_LEN (K_DIM / KSPL)                  // 512
#define LORA_BLKS (M_DIM / 128 * KSPL)         // 512
#define DEQ_BLKS (N_DIM * K_DIM / 2048)        // 8192

// ---- device scratch ----
__device__ float g_ax[M_DIM * R_DIM];
__device__ float g_axp[M_DIM * R_DIM * KSPL];
__device__ __half g_xh[(size_t)M_DIM * K_DIM];
__device__ __half g_wh[(size_t)N_DIM * K_DIM];

__constant__ float c_nf4[16] = {
    -1.0f, -0.6961928009986877f, -0.5250730514526367f, -0.39491748809814453f,
    -0.28444138169288635f, -0.18477343022823334f, -0.09105003625154495f, 0.0f,
    0.07958029955625534f, 0.16093020141124725f, 0.24611230194568634f,
    0.33791524171829224f, 0.44070982933044434f, 0.5626170039176941f,
    0.7229568362236023f, 1.0f};

// ---------------------------------------------------------------------------
__device__ __forceinline__ uint32_t smem_u32(const void* p) {
  return (uint32_t)__cvta_generic_to_shared((void*)p);
}
__device__ __forceinline__ uint32_t swz(uint32_t off) {
  return off ^ (((off >> 7) & 7u) << 4);
}
__device__ __forceinline__ void cpa16(uint32_t s, const void* g) {
  asm volatile("cp.async.cg.shared.global [%0], [%1], 16;" :: "r"(s), "l"(g));
}
__device__ __forceinline__ void ldsm4(uint32_t (&r)[4], uint32_t addr) {
  asm volatile(
      "ldmatrix.sync.aligned.m8n8.x4.shared.b16 {%0,%1,%2,%3}, [%4];"
      : "=r"(r[0]), "=r"(r[1]), "=r"(r[2]), "=r"(r[3]) : "r"(addr));
}
__device__ __forceinline__ void mma_f16(float (&d)[4], const uint32_t (&a)[4],
                                        uint32_t b0, uint32_t b1) {
  asm volatile(
      "mma.sync.aligned.m16n8k16.row.col.f32.f16.f16.f32 "
      "{%0,%1,%2,%3}, {%4,%5,%6,%7}, {%8,%9}, {%0,%1,%2,%3};"
      : "+f"(d[0]), "+f"(d[1]), "+f"(d[2]), "+f"(d[3])
      : "r"(a[0]), "r"(a[1]), "r"(a[2]), "r"(a[3]), "r"(b0), "r"(b1));
}

// ---------------------------------------------------------------------------
// Fused precompute.
// Blocks [0, LORA_BLKS): 128 m-rows x 512 k; x->fp16 (g_xh + smem) and
//   lora partials via tensor cores.
// Blocks [LORA_BLKS, +DEQ_BLKS): NF4 dequant, 8 codes/thread.
// ---------------------------------------------------------------------------
__global__ __launch_bounds__(256) void fused_pre_kernel(
    const float* __restrict__ x, const int* __restrict__ codes,
    const float* __restrict__ absmax, const float* __restrict__ A) {
  __shared__ char smbuf[16384 + 2048];  // Xs [128 x 128B] + As [16 x 128B]
  const int tid = threadIdx.x;

  if (blockIdx.x >= LORA_BLKS) {
    // ---- dequant: 8 codes per thread ----
    __shared__ float lut[16];
    if (tid < 16) lut[tid] = c_nf4[tid];
    __syncthreads();
    size_t i8 = (size_t)(blockIdx.x - LORA_BLKS) * 256 + tid;
    const int4* c4p = (const int4*)codes;
    int4 c0 = c4p[i8 * 2];
    int4 c1 = c4p[i8 * 2 + 1];
    size_t e0 = i8 * 8;
    int row = (int)(e0 >> 12);
    int col = (int)(e0 & 4095);
    float am = absmax[row * (K_DIM / 64) + (col >> 6)];
    __half h[8] = {
        __float2half_rn(lut[c0.x] * am), __float2half_rn(lut[c0.y] * am),
        __float2half_rn(lut[c0.z] * am), __float2half_rn(lut[c0.w] * am),
        __float2half_rn(lut[c1.x] * am), __float2half_rn(lut[c1.y] * am),
        __float2half_rn(lut[c1.z] * am), __float2half_rn(lut[c1.w] * am)};
    *(uint4*)&g_wh[e0] = *(uint4*)h;
    return;
  }

  // ---- lora via tensor cores: 128 m-rows x 512 k ----
  const int bx = blockIdx.x;
  const int m0 = (bx & 63) * 128;
  const int ks = bx >> 6;
  const int wid = tid >> 5;
  const int lane = tid & 31;
  const int rl = lane & 15;
  const int chalf = (lane >> 4) * 16;
  const uint32_t sbase = smem_u32(smbuf);

  const int xrow = wid * 16 + rl;
  const uint32_t offX = (uint32_t)(xrow * 128 + (chalf ^ ((xrow & 7) << 4)));
  const uint32_t offA =
      16384u + (uint32_t)(rl * 128 + (chalf ^ ((rl & 7) << 4)));

  float acc[2][4];
#pragma unroll
  for (int i = 0; i < 2; i++)
#pragma unroll
    for (int e = 0; e < 4; e++) acc[i][e] = 0.f;

  for (int c8 = 0; c8 < 8; c8++) {
    const int kc = ks * KS_LEN + c8 * 64;
    {
      int r = tid >> 4;
      int c4 = (tid & 15) * 4;
      float4 v = *(const float4*)&A[r * K_DIM + kc + c4];
      __half h[4] = {__float2half_rn(v.x), __float2half_rn(v.y),
                     __float2half_rn(v.z), __float2half_rn(v.w)};
      *(uint2*)(smbuf + 16384 + swz((uint32_t)(r * 128 + c4 * 2))) =
          *(uint2*)h;
    }
#pragma unroll
    for (int i = 0; i < 8; i++) {
      int idx = tid + i * 256;
      int row = idx >> 4;
      int c4 = (idx & 15) * 4;
      size_t gofs = (size_t)(m0 + row) * K_DIM + kc + c4;
      float4 v = *(const float4*)&x[gofs];
      __half h[4] = {__float2half_rn(v.x), __float2half_rn(v.y),
                     __float2half_rn(v.z), __float2half_rn(v.w)};
      *(uint2*)&g_xh[gofs] = *(uint2*)h;
      *(uint2*)(smbuf + swz((uint32_t)(row * 128 + c4 * 2))) = *(uint2*)h;
    }
    __syncthreads();
#pragma unroll
    for (int kst = 0; kst < 4; kst++) {
      const uint32_t kx = (uint32_t)(kst << 5);
      uint32_t af[4], bf[4];
      ldsm4(af, sbase + (offX ^ kx));
      ldsm4(bf, sbase + (offA ^ kx));
      mma_f16(acc[0], af, bf[0], bf[2]);
      mma_f16(acc[1], af, bf[1], bf[3]);
    }
    __syncthreads();
  }

  const int mrow = m0 + wid * 16 + (lane >> 2);
  const int cb = (lane & 3) * 2;
#pragma unroll
  for (int ni = 0; ni < 2; ni++) {
    int rc = cb + ni * 8;
    g_axp[((size_t)mrow * R_DIM + rc) * KSPL + ks] = acc[ni][0];
    g_axp[((size_t)mrow * R_DIM + rc + 1) * KSPL + ks] = acc[ni][1];
    g_axp[((size_t)(mrow + 8) * R_DIM + rc) * KSPL + ks] = acc[ni][2];
    g_axp[((size_t)(mrow + 8) * R_DIM + rc + 1) * KSPL + ks] = acc[ni][3];
  }
}

__global__ __launch_bounds__(256) void lora_ax_reduce_kernel() {
  int j = blockIdx.x * 256 + threadIdx.x;
  const float4* p = (const float4*)&g_axp[(size_t)j * KSPL];
  float4 a = p[0], b = p[1];
  g_ax[j] = 2.0f * (((a.x + a.y) + (a.z + a.w)) + ((b.x + b.y) + (b.z + b.w)));
}

// ---------------------------------------------------------------------------
// Main HMMA GEMM: 128x128 tile, BK=64, 3-stage cp.async pipeline, SW128 smem.
// ---------------------------------------------------------------------------
__global__ __launch_bounds__(256, 2) void qlora_mma_kernel(
    const float* __restrict__ Bw, float* __restrict__ out) {
  extern __shared__ char sm[];
  const int tid = threadIdx.x;
  const int wid = tid >> 5;
  const int lane = tid & 31;
  const int n0 = blockIdx.x * TN;
  const int m0 = blockIdx.y * TM;
  const int warp_m0 = (wid >> 2) * 64;
  const int warp_n0 = (wid & 3) * 32;
  const uint32_t sbase = smem_u32(sm);

  const __half* Xh = g_xh + (size_t)m0 * K_DIM;
  const __half* Wh = g_wh + (size_t)n0 * K_DIM;

  uint32_t so[4];
  size_t go[4];
#pragma unroll
  for (int j = 0; j < 4; j++) {
    int c = tid + j * 256;
    int row = c >> 3, cc = c & 7;
    go[j] = (size_t)row * K_DIM + cc * 8;
    so[j] = swz((uint32_t)(row * 128 + cc * 16));
  }

#define LOAD_STAGE(SB, KT)                                                     \
  do {                                                                         \
    uint32_t _sb = (SB);                                                       \
    int _kt = (KT);                                                            \
    cpa16(_sb + so[0], Xh + go[0] + _kt);                                      \
    cpa16(_sb + so[1], Xh + go[1] + _kt);                                      \
    cpa16(_sb + so[2], Xh + go[2] + _kt);                                      \
    cpa16(_sb + so[3], Xh + go[3] + _kt);                                      \
    cpa16(_sb + TILEB + so[0], Wh + go[0] + _kt);                              \
    cpa16(_sb + TILEB + so[1], Wh + go[1] + _kt);                              \
    cpa16(_sb + TILEB + so[2], Wh + go[2] + _kt);                              \
    cpa16(_sb + TILEB + so[3], Wh + go[3] + _kt);                              \
  } while (0)

  const int rl = lane & 15;
  const int chalf = (lane >> 4) * 16;
  uint32_t offA[4], offB[2];
#pragma unroll
  for (int mi = 0; mi < 4; mi++) {
    int row = warp_m0 + mi * 16 + rl;
    offA[mi] = (uint32_t)(row * 128 + (chalf ^ ((row & 7) << 4)));
  }
#pragma unroll
  for (int np = 0; np < 2; np++) {
    int row = warp_n0 + np * 16 + rl;
    offB[np] = TILEB + (uint32_t)(row * 128 + (chalf ^ ((row & 7) << 4)));
  }

  float acc[4][4][4];
#pragma unroll
  for (int i = 0; i < 4; i++)
#pragma unroll
    for (int j = 0; j < 4; j++)
#pragma unroll
      for (int e = 0; e < 4; e++) acc[i][j][e] = 0.f;

  LOAD_STAGE(sbase, 0);
  asm volatile("cp.async.commit_group;" ::: "memory");
  LOAD_STAGE(sbase + STAGEB, BK);
  asm volatile("cp.async.commit_group;" ::: "memory");

  int slot = 0, wslot = 2;
  for (int k = 0; k < NK; k++) {
    asm volatile("cp.async.wait_group 1;" ::: "memory");
    __syncthreads();

    if (k + 2 < NK) LOAD_STAGE(sbase + wslot * STAGEB, (k + 2) * BK);
    asm volatile("cp.async.commit_group;" ::: "memory");

    const uint32_t sb = sbase + slot * STAGEB;

    uint32_t bh[2][2][4];
    ldsm4(bh[0][0], sb + offB[0]);
    ldsm4(bh[0][1], sb + offB[1]);
#pragma unroll
    for (int ks = 0; ks < 4; ks++) {
      const uint32_t kx = (uint32_t)(ks << 5);
      const int cur = ks & 1;
      uint32_t af[4][4];
#pragma unroll
      for (int mi = 0; mi < 4; mi++) ldsm4(af[mi], sb + (offA[mi] ^ kx));
      if (ks < 3) {
        const uint32_t kxn = (uint32_t)((ks + 1) << 5);
        ldsm4(bh[cur ^ 1][0], sb + (offB[0] ^ kxn));
        ldsm4(bh[cur ^ 1][1], sb + (offB[1] ^ kxn));
      }
#pragma unroll
      for (int mi = 0; mi < 4; mi++)
#pragma unroll
        for (int ni = 0; ni < 4; ni++)
          mma_f16(acc[mi][ni], af[mi], bh[cur][ni >> 1][ni & 1],
                  bh[cur][ni >> 1][2 + (ni & 1)]);
    }

    slot = (slot == 2) ? 0 : slot + 1;
    wslot = (wslot == 2) ? 0 : wslot + 1;
  }

  // ---- epilogue: LoRA + store ----
  asm volatile("cp.async.wait_all;" ::: "memory");
  __syncthreads();

  float* axs = (float*)sm;                    // [128][16]
  float* bs = (float*)(sm + 128 * 16 * 4);    // [128] stride 17
  for (int j = tid; j < TM * R_DIM; j += 256)
    axs[j] = g_ax[(size_t)m0 * R_DIM + j];
  for (int j = tid; j < TN * R_DIM; j += 256) {
    int col = j >> 4, r = j & 15;
    bs[col * 17 + r] = Bw[(size_t)(n0 + col) * R_DIM + r];
  }
  __syncthreads();

  const int r0 = lane >> 2;
  const int cbase = warp_n0 + (lane & 3) * 2;
#pragma unroll
  for (int mi = 0; mi < 4; mi++) {
#pragma unroll
    for (int half = 0; half < 2; half++) {
      const int mr = warp_m0 + mi * 16 + r0 + half * 8;
      float axr[16];
      *(float4*)&axr[0] = *(const float4*)&axs[mr * 16];
      *(float4*)&axr[4] = *(const float4*)&axs[mr * 16 + 4];
      *(float4*)&axr[8] = *(const float4*)&axs[mr * 16 + 8];
      *(float4*)&axr[12] = *(const float4*)&axs[mr * 16 + 12];
      float* orow = out + (size_t)(m0 + mr) * N_DIM + n0;
#pragma unroll
      for (int ni = 0; ni < 4; ni++) {
        const int c = cbase + ni * 8;
        const float* b0 = &bs[c * 17];
        const float* b1 = &bs[(c + 1) * 17];
        float l0 = 0.f, l1 = 0.f;
#pragma unroll
        for (int r = 0; r < 16; r++) {
          l0 += axr[r] * b0[r];
          l1 += axr[r] * b1[r];
        }
        float2 v = make_float2(acc[mi][ni][half * 2 + 0] + l0,
                               acc[mi][ni][half * 2 + 1] + l1);
        *(float2*)&orow[c] = v;
      }
    }
  }
}

// ---------------------------------------------------------------------------
extern "C" void kernel_launch(void* const* d_in, const int* in_sizes, int n_in,
                              void* d_out, int out_size) {
  const float* x = (const float*)d_in[0];
  const int* codes = (const int*)d_in[1];
  const float* absmax = (const float*)d_in[2];
  const float* A = (const float*)d_in[3];
  const float* Bw = (const float*)d_in[4];
  float* out = (float*)d_out;

  cudaFuncSetAttribute(qlora_mma_kernel,
                       cudaFuncAttributeMaxDynamicSharedMemorySize, SMEMB);

  fused_pre_kernel<<<LORA_BLKS + DEQ_BLKS, 256>>>(x, codes, absmax, A);
  lora_ax_reduce_kernel<<<(M_DIM * R_DIM) / 256, 256>>>();

  dim3 grid(N_DIM / TN, M_DIM / TM);
  qlora_mma_kernel<<<grid, 256, SMEMB>>>(Bw, out);
}